// round 14
// baseline (speedup 1.0000x reference)
#include <cuda_runtime.h>

// StreamNet_K3_S1: fused halo-concat + 3x3 VALID conv + bias.
// x:[8,32,256,256] rbuf:[8,32,256,2] bbuf:[8,32,2,258] W:[32,32,3,3] bias:[32]
// out:[8,32,256,256]
//
// R13: kill register spills. 512-thread CTAs, thread = 1 c_out x 4 rows x
// 4 cols (acc 16, live ~45 regs, fits well under cap). Same 8x32 tile/block,
// same 46KB smem; 2 CTAs/SM -> 32 warps/SM (occupancy unchanged vs R12).

#define BATCH 8
#define CH 32
#define P 256
#define PP (P + 2)

#define TH 8              // output rows per block
#define TW 32             // output cols per block
#define TRH 4             // output rows per thread
#define IN_H (TH + 2)     // 10 padded rows in tile
#define IN_W (TW + 2)     // 34 padded cols in tile
#define IN_WP 36          // smem row stride (floats), keeps 16B alignment

#define NTHREADS 512

#define SMEM_IN_FLOATS (CH * IN_H * IN_WP)   // 11520
#define SMEM_BYTES (SMEM_IN_FLOATS * 4)      // 46080 B -> 2 CTAs/SM at 512 thr

__global__ __launch_bounds__(NTHREADS, 2)
void streamnet_conv3x3_kernel(const float* __restrict__ x,
                              const float* __restrict__ rbuf,
                              const float* __restrict__ bbuf,
                              const float* __restrict__ Wt,
                              const float* __restrict__ bias,
                              float* __restrict__ out)
{
    extern __shared__ float smem[];
    float* sIn = smem;                       // [CH][IN_H][IN_WP]

    const int tid   = threadIdx.x;
    const int b     = blockIdx.z;
    const int r0    = blockIdx.y * TH;       // output row base (block)
    const int c0blk = blockIdx.x * TW;       // output col base (block)

    // ---- load padded input tile: 32ci x 10 x 34, halo-mapped ----
    for (int t = tid; t < CH * IN_H * IN_W; t += NTHREADS) {
        int ci   = t / (IN_H * IN_W);
        int rem  = t - ci * (IN_H * IN_W);
        int y    = rem / IN_W;
        int xcol = rem - y * IN_W;
        int pr   = r0 + y;                   // padded row  [0, 258)
        int pc   = c0blk + xcol;             // padded col  [0, 258)
        float v;
        if (pr < 2) {
            v = bbuf[((b * CH + ci) * 2 + pr) * PP + pc];
        } else {
            int xr = pr - 2;
            if (pc < 2) {
                v = rbuf[((b * CH + ci) * P + xr) * 2 + pc];
            } else {
                int xc = pc - 2;
                v = (xc == P - 1) ? 0.0f
                                  : x[((size_t)(b * CH + ci) * P + xr) * P + xc];
            }
        }
        sIn[ci * (IN_H * IN_WP) + y * IN_WP + xcol] = v;
    }
    __syncthreads();

    // ---- compute: thread = 1 c_out x 4 rows x 4 cols ----
    // tid = co*16 + rhalf*8 + cg  (cg in low 3 bits -> contiguous 128B stores)
    const int cg    = tid & 7;
    const int rhalf = (tid >> 3) & 1;
    const int co    = tid >> 4;
    const int c0    = cg * 4;                // col offset within tile
    const int rbase = rhalf * TRH;           // row offset within tile

    float acc[TRH][4];
    const float bv = __ldg(bias + co);
    #pragma unroll
    for (int r = 0; r < TRH; r++)
        #pragma unroll
        for (int c = 0; c < 4; c++)
            acc[r][c] = bv;

    // weights straight from global: 36KB total, shared by all blocks ->
    // L1/L2 resident after wave 1; threads of same co broadcast.
    const float* wbase = Wt + co * (CH * 9);

    #pragma unroll 1
    for (int ci = 0; ci < CH; ci++) {
        const float* ib = sIn + ci * (IN_H * IN_WP) + rbase * IN_WP + c0;

        float w[9];
        #pragma unroll
        for (int k = 0; k < 9; k++) w[k] = __ldg(wbase + ci * 9 + k);

        // row-streaming over the 6 padded rows feeding this thread's 4 rows:
        // padded row (rbase+y) feeds output rows (rbase + y-2 .. rbase + y)
        #pragma unroll
        for (int y = 0; y < TRH + 2; y++) {
            float row[6];
            {
                const float* rp = ib + y * IN_WP;     // 16B-aligned
                float4 t4 = *reinterpret_cast<const float4*>(rp);
                float2 t2 = *reinterpret_cast<const float2*>(rp + 4);
                row[0] = t4.x; row[1] = t4.y; row[2] = t4.z; row[3] = t4.w;
                row[4] = t2.x; row[5] = t2.y;
            }
            #pragma unroll
            for (int kh = 0; kh < 3; kh++) {
                const int r = y - kh;                 // compile-time resolved
                if (r >= 0 && r < TRH) {
                    #pragma unroll
                    for (int kw = 0; kw < 3; kw++) {
                        const float wv = w[kh * 3 + kw];
                        #pragma unroll
                        for (int c = 0; c < 4; c++)
                            acc[r][c] = fmaf(row[c + kw], wv, acc[r][c]);
                    }
                }
            }
        }
    }

    // ---- store: float4 per row, contiguous 128B per 8-thread group ----
    #pragma unroll
    for (int r = 0; r < TRH; r++) {
        float4 v = make_float4(acc[r][0], acc[r][1], acc[r][2], acc[r][3]);
        float* op = out + ((size_t)(b * CH + co) * P + (r0 + rbase + r)) * P
                        + (c0blk + c0);
        *reinterpret_cast<float4*>(op) = v;
    }
}

extern "C" void kernel_launch(void* const* d_in, const int* in_sizes, int n_in,
                              void* d_out, int out_size)
{
    (void)in_sizes; (void)n_in; (void)out_size;
    const float* x    = (const float*)d_in[0];
    const float* rbuf = (const float*)d_in[1];
    const float* bbuf = (const float*)d_in[2];
    const float* Wt   = (const float*)d_in[3];
    const float* bias = (const float*)d_in[4];
    float* out = (float*)d_out;

    static bool inited = false;
    if (!inited) {
        cudaFuncSetAttribute(streamnet_conv3x3_kernel,
                             cudaFuncAttributeMaxDynamicSharedMemorySize, SMEM_BYTES);
        inited = true;
    }

    dim3 grid(P / TW, P / TH, BATCH);   // 8 x 32 x 8 = 2048 blocks
    streamnet_conv3x3_kernel<<<grid, NTHREADS, SMEM_BYTES>>>(x, rbuf, bbuf, Wt, bias, out);
}

// round 15
// speedup vs baseline: 1.1036x; 1.1036x over previous
#include <cuda_runtime.h>

// StreamNet_K3_S1: fused halo-concat + 3x3 VALID conv + bias.
// x:[8,32,256,256] rbuf:[8,32,256,2] bbuf:[8,32,2,258] W:[32,32,3,3] bias:[32]
// out:[8,32,256,256]
//
// R14: weight repack [co][ci][k] -> [ci][k][co] via pre-kernel into __device__
// scratch. Warp weight loads become 4-consecutive-float (1 sector, 8-way
// broadcast) instead of 4x128B-line gathers -> L1 wavefront demand /~2.
// Compute: R8 config (256 thr, 4 CTAs/SM) + R12 row-streaming body.

#define BATCH 8
#define CH 32
#define P 256
#define PP (P + 2)

#define TH 8              // output rows per block
#define TW 32             // output cols per block
#define IN_H (TH + 2)     // 10 padded rows in tile
#define IN_W (TW + 2)     // 34 padded cols in tile
#define IN_WP 36          // smem row stride (floats), keeps 16B alignment

#define SMEM_IN_FLOATS (CH * IN_H * IN_WP)   // 11520
#define SMEM_BYTES (SMEM_IN_FLOATS * 4)      // 46080 B -> 4 CTAs/SM

// repacked weights: [ci][k][co]  (co contiguous)
__device__ float g_wrepack[CH * 9 * CH];     // 9216 floats

__global__ void repack_weights_kernel(const float* __restrict__ Wt)
{
    int idx = blockIdx.x * blockDim.x + threadIdx.x;   // 0 .. 9215
    if (idx < CH * CH * 9) {
        int co   = idx / (CH * 9);
        int rest = idx - co * (CH * 9);                // ci*9 + k
        int ci   = rest / 9;
        int k    = rest - ci * 9;
        g_wrepack[(ci * 9 + k) * CH + co] = Wt[idx];
    }
}

__global__ __launch_bounds__(256, 4)
void streamnet_conv3x3_kernel(const float* __restrict__ x,
                              const float* __restrict__ rbuf,
                              const float* __restrict__ bbuf,
                              const float* __restrict__ bias,
                              float* __restrict__ out)
{
    extern __shared__ float smem[];
    float* sIn = smem;                       // [CH][IN_H][IN_WP]

    const int tid   = threadIdx.x;
    const int b     = blockIdx.z;
    const int r0    = blockIdx.y * TH;       // output row base
    const int c0blk = blockIdx.x * TW;       // output col base

    // ---- load padded input tile: 32ci x 10 x 34, halo-mapped ----
    for (int t = tid; t < CH * IN_H * IN_W; t += 256) {
        int ci   = t / (IN_H * IN_W);
        int rem  = t - ci * (IN_H * IN_W);
        int y    = rem / IN_W;
        int xcol = rem - y * IN_W;
        int pr   = r0 + y;                   // padded row  [0, 258)
        int pc   = c0blk + xcol;             // padded col  [0, 258)
        float v;
        if (pr < 2) {
            v = bbuf[((b * CH + ci) * 2 + pr) * PP + pc];
        } else {
            int xr = pr - 2;
            if (pc < 2) {
                v = rbuf[((b * CH + ci) * P + xr) * 2 + pc];
            } else {
                int xc = pc - 2;
                v = (xc == P - 1) ? 0.0f
                                  : x[((size_t)(b * CH + ci) * P + xr) * P + xc];
            }
        }
        sIn[ci * (IN_H * IN_WP) + y * IN_WP + xcol] = v;
    }
    __syncthreads();

    // ---- compute: each thread = 1 c_out, 8 rows x 4 cols ----
    const int co = tid >> 3;
    const int c0 = (tid & 7) * 4;            // col offset within tile

    float acc[TH][4];
    const float bv = __ldg(bias + co);
    #pragma unroll
    for (int r = 0; r < TH; r++)
        #pragma unroll
        for (int c = 0; c < 4; c++)
            acc[r][c] = bv;

    // repacked weights: warp reads 4 consecutive floats per (ci,k)
    // (co = tid>>3 spans 4 values in a warp) -> 1 sector, 8-way broadcast.
    const float* wrp = g_wrepack + co;

    #pragma unroll 1
    for (int ci = 0; ci < CH; ci++) {
        const float* ib = sIn + ci * (IN_H * IN_WP) + c0;

        float w[9];
        #pragma unroll
        for (int k = 0; k < 9; k++)
            w[k] = __ldg(wrp + (ci * 9 + k) * CH);

        // row-streaming: padded input row y feeds output rows y-2..y
        #pragma unroll
        for (int y = 0; y < IN_H; y++) {
            float row[6];
            {
                const float* rp = ib + y * IN_WP;     // 16B-aligned
                float4 t4 = *reinterpret_cast<const float4*>(rp);
                float2 t2 = *reinterpret_cast<const float2*>(rp + 4);
                row[0] = t4.x; row[1] = t4.y; row[2] = t4.z; row[3] = t4.w;
                row[4] = t2.x; row[5] = t2.y;
            }
            #pragma unroll
            for (int kh = 0; kh < 3; kh++) {
                const int r = y - kh;                 // compile-time resolved
                if (r >= 0 && r < TH) {
                    #pragma unroll
                    for (int kw = 0; kw < 3; kw++) {
                        const float wv = w[kh * 3 + kw];
                        #pragma unroll
                        for (int c = 0; c < 4; c++)
                            acc[r][c] = fmaf(row[c + kw], wv, acc[r][c]);
                    }
                }
            }
        }
    }

    // ---- store: float4 per row, contiguous 128B per 8-thread group ----
    #pragma unroll
    for (int r = 0; r < TH; r++) {
        float4 v = make_float4(acc[r][0], acc[r][1], acc[r][2], acc[r][3]);
        float* op = out + ((size_t)(b * CH + co) * P + (r0 + r)) * P + (c0blk + c0);
        *reinterpret_cast<float4*>(op) = v;
    }
}

extern "C" void kernel_launch(void* const* d_in, const int* in_sizes, int n_in,
                              void* d_out, int out_size)
{
    (void)in_sizes; (void)n_in; (void)out_size;
    const float* x    = (const float*)d_in[0];
    const float* rbuf = (const float*)d_in[1];
    const float* bbuf = (const float*)d_in[2];
    const float* Wt   = (const float*)d_in[3];
    const float* bias = (const float*)d_in[4];
    float* out = (float*)d_out;

    static bool inited = false;
    if (!inited) {
        cudaFuncSetAttribute(streamnet_conv3x3_kernel,
                             cudaFuncAttributeMaxDynamicSharedMemorySize, SMEM_BYTES);
        inited = true;
    }

    // 1) repack weights into [ci][k][co] scratch (graph-capturable launch)
    repack_weights_kernel<<<36, 256>>>(Wt);

    // 2) main conv
    dim3 grid(P / TW, P / TH, BATCH);   // 8 x 32 x 8 = 2048 blocks
    streamnet_conv3x3_kernel<<<grid, 256, SMEM_BYTES>>>(x, rbuf, bbuf, bias, out);
}